// round 3
// baseline (speedup 1.0000x reference)
#include <cuda_runtime.h>
#include <cstdint>

#define B_SESS 4096
#define MAX_LEN 200
#define E 112
#define N_ITEMS 100000
#define LAYERS 3
#define KSPLIT 8
#define KCHUNK (B_SESS / KSPLIT)   // 512

// Scratch (no allocations allowed in kernel_launch)
__device__ float g_s[B_SESS * E];                 // current session_emb
__device__ float g_t[B_SESS * E];                 // s @ W^T
__device__ float g_acc[B_SESS * E];               // running accumulator
__device__ float g_part[KSPLIT * B_SESS * E];     // split-K partials
__device__ float g_d[B_SESS];                     // diag of D

// ---------------------------------------------------------------------------
// 1. Fused ragged gather + mean pool. One block per session.
//    idx==0 -> zero row (padding); idx>=1 -> item_embedding[idx-1].
// ---------------------------------------------------------------------------
__global__ void gather_mean_kernel(const float* __restrict__ emb,
                                   const int* __restrict__ items,
                                   const float* __restrict__ slen) {
    __shared__ int sidx[MAX_LEN];
    int b = blockIdx.x;
    int tid = threadIdx.x;
    for (int i = tid; i < MAX_LEN; i += blockDim.x)
        sidx[i] = items[(size_t)b * MAX_LEN + i];
    __syncthreads();
    if (tid < E) {
        float acc = 0.0f;
        #pragma unroll 4
        for (int t = 0; t < MAX_LEN; ++t) {
            int idx = sidx[t];
            if (idx > 0 && idx <= N_ITEMS)
                acc += emb[((size_t)(idx - 1)) * E + tid];
        }
        float v = acc / slen[b];
        g_s[(size_t)b * E + tid] = v;
        g_acc[(size_t)b * E + tid] = v;   // layer-0 term of the average
    }
}

// ---------------------------------------------------------------------------
// 2. Extract diag(D).
// ---------------------------------------------------------------------------
__global__ void diag_kernel(const float* __restrict__ D) {
    int i = blockIdx.x * blockDim.x + threadIdx.x;
    if (i < B_SESS)
        g_d[i] = D[(size_t)i * B_SESS + i];
}

// ---------------------------------------------------------------------------
// 3. t = s @ W^T, W is [out,in] (torch layout). One block per row of s.
// ---------------------------------------------------------------------------
__global__ void small_mm_kernel(const float* __restrict__ W) {
    __shared__ float srow[E];
    int b = blockIdx.x;
    int o = threadIdx.x;   // blockDim.x == E
    srow[o] = g_s[(size_t)b * E + o];
    __syncthreads();
    const float4* w4 = reinterpret_cast<const float4*>(W + (size_t)o * E);
    const float4* s4 = reinterpret_cast<const float4*>(srow);
    float acc = 0.0f;
    #pragma unroll
    for (int i = 0; i < E / 4; ++i) {
        float4 w = w4[i];
        float4 s = s4[i];
        acc = fmaf(w.x, s.x, acc);
        acc = fmaf(w.y, s.y, acc);
        acc = fmaf(w.z, s.z, acc);
        acc = fmaf(w.w, s.w, acc);
    }
    g_t[(size_t)b * E + o] = acc;
}

// ---------------------------------------------------------------------------
// 4. Split-K big matmul: part[ck] = A[:, ck*512:(ck+1)*512] @ t[ck*512:...]
//    BM=128 rows/block, BK=32, 256 threads, 8x7 outputs per thread.
//    grid = (32, KSPLIT)
// ---------------------------------------------------------------------------
__global__ void __launch_bounds__(256, 2)
big_mm_kernel(const float* __restrict__ A) {
    __shared__ float As[128][33];     // pad -> conflict-free column reads
    __shared__ float Xs[32][116];     // pad -> stride-7 col reads conflict-free

    const int tid = threadIdx.x;
    const int tx = tid & 15;          // 16 col groups of 7
    const int ty = tid >> 4;          // 16 row groups (rows ty + 16*i)
    const int row0 = blockIdx.x * 128;
    const int kbase = blockIdx.y * KCHUNK;

    float acc[8][7];
    #pragma unroll
    for (int i = 0; i < 8; ++i)
        #pragma unroll
        for (int j = 0; j < 7; ++j) acc[i][j] = 0.0f;

    for (int k0 = kbase; k0 < kbase + KCHUNK; k0 += 32) {
        // A tile: 128x32 = 1024 float4
        for (int i = tid; i < 1024; i += 256) {
            int r = i >> 3, c4 = i & 7;
            float4 v = *reinterpret_cast<const float4*>(
                &A[(size_t)(row0 + r) * B_SESS + k0 + c4 * 4]);
            As[r][c4 * 4 + 0] = v.x; As[r][c4 * 4 + 1] = v.y;
            As[r][c4 * 4 + 2] = v.z; As[r][c4 * 4 + 3] = v.w;
        }
        // X tile: 32x112 = 896 float4
        for (int i = tid; i < 896; i += 256) {
            int r = i / 28, c4 = i % 28;
            float4 v = *reinterpret_cast<const float4*>(
                &g_t[(size_t)(k0 + r) * E + c4 * 4]);
            Xs[r][c4 * 4 + 0] = v.x; Xs[r][c4 * 4 + 1] = v.y;
            Xs[r][c4 * 4 + 2] = v.z; Xs[r][c4 * 4 + 3] = v.w;
        }
        __syncthreads();

        #pragma unroll 4
        for (int kk = 0; kk < 32; ++kk) {
            float a[8], xv[7];
            #pragma unroll
            for (int i = 0; i < 8; ++i) a[i] = As[ty + 16 * i][kk];
            #pragma unroll
            for (int j = 0; j < 7; ++j) xv[j] = Xs[kk][tx * 7 + j];
            #pragma unroll
            for (int i = 0; i < 8; ++i)
                #pragma unroll
                for (int j = 0; j < 7; ++j)
                    acc[i][j] = fmaf(a[i], xv[j], acc[i][j]);
        }
        __syncthreads();
    }

    float* part = g_part + (size_t)blockIdx.y * B_SESS * E;
    #pragma unroll
    for (int i = 0; i < 8; ++i) {
        int r = row0 + ty + 16 * i;
        #pragma unroll
        for (int j = 0; j < 7; ++j)
            part[(size_t)r * E + tx * 7 + j] = acc[i][j];
    }
}

// ---------------------------------------------------------------------------
// 5. Reduce split-K partials, apply diagonal scale -> g_s (next session_emb)
// ---------------------------------------------------------------------------
__global__ void reducek_kernel() {
    int idx = blockIdx.x * blockDim.x + threadIdx.x;
    if (idx >= B_SESS * E) return;
    float sum = 0.0f;
    #pragma unroll
    for (int c = 0; c < KSPLIT; ++c)
        sum += g_part[(size_t)c * B_SESS * E + idx];
    int r = idx / E;
    g_s[idx] = g_d[r] * sum;
}

// ---------------------------------------------------------------------------
// 6. Row L2-normalize g_s and add into g_acc. One warp per row.
// ---------------------------------------------------------------------------
__global__ void norm_acc_kernel() {
    int warp = threadIdx.x >> 5;
    int lane = threadIdx.x & 31;
    int r = blockIdx.x * 4 + warp;
    if (r >= B_SESS) return;
    const float4* row = reinterpret_cast<const float4*>(g_s + (size_t)r * E);
    float4 v = make_float4(0.f, 0.f, 0.f, 0.f);
    if (lane < E / 4) v = row[lane];
    float ss = v.x * v.x + v.y * v.y + v.z * v.z + v.w * v.w;
    #pragma unroll
    for (int o = 16; o; o >>= 1) ss += __shfl_xor_sync(0xffffffffu, ss, o);
    float f = 1.0f / fmaxf(sqrtf(ss), 1e-12f);
    if (lane < E / 4) {
        float4* arow = reinterpret_cast<float4*>(g_acc + (size_t)r * E);
        float4 a = arow[lane];
        a.x = fmaf(v.x, f, a.x);
        a.y = fmaf(v.y, f, a.y);
        a.z = fmaf(v.z, f, a.z);
        a.w = fmaf(v.w, f, a.w);
        arow[lane] = a;
    }
}

// ---------------------------------------------------------------------------
// 7. out = g_acc / (LAYERS + 1)
// ---------------------------------------------------------------------------
__global__ void scale_out_kernel(float* __restrict__ out) {
    int idx = blockIdx.x * blockDim.x + threadIdx.x;
    if (idx < B_SESS * E)
        out[idx] = g_acc[idx] * 0.25f;
}

// ---------------------------------------------------------------------------
extern "C" void kernel_launch(void* const* d_in, const int* in_sizes, int n_in,
                              void* d_out, int out_size) {
    const float* emb   = (const float*)d_in[0];     // [100000,112]
    const float* D     = (const float*)d_in[1];     // [4096,4096]
    const float* A     = (const float*)d_in[2];     // [4096,4096]
    const float* slen  = (const float*)d_in[3];     // [4096,1]
    const float* Ws    = (const float*)d_in[4];     // [3,112,112]
    const int*   items = (const int*)d_in[5];       // [4096,200] int32 (jax x64 off)
    float* out = (float*)d_out;

    gather_mean_kernel<<<B_SESS, 128>>>(emb, items, slen);
    diag_kernel<<<(B_SESS + 255) / 256, 256>>>(D);

    for (int l = 0; l < LAYERS; ++l) {
        small_mm_kernel<<<B_SESS, E>>>(Ws + (size_t)l * E * E);
        big_mm_kernel<<<dim3(B_SESS / 128, KSPLIT), 256>>>(A);
        reducek_kernel<<<(B_SESS * E + 255) / 256, 256>>>();
        norm_acc_kernel<<<B_SESS / 4, 128>>>();
    }

    scale_out_kernel<<<(B_SESS * E + 255) / 256, 256>>>(out);
}

// round 5
// speedup vs baseline: 2.1300x; 2.1300x over previous
#include <cuda_runtime.h>
#include <cstdint>

#define B_SESS 4096
#define MAX_LEN 200
#define E 112
#define N_ITEMS 100000
#define LAYERS 3
#define KSPLIT 8
#define KCHUNK (B_SESS / KSPLIT)   // 512
#define BK 32
#define NSTAGE (KCHUNK / BK)       // 16

// smem staging (uint32 units). Strides picked for conflict-free fragment LDS.
#define AS_STRIDE 36
#define BS_STRIDE 120
#define AS_U32 (128 * AS_STRIDE)
#define BS_U32 (32 * BS_STRIDE)
#define SMEM_BYTES ((2 * AS_U32 + 2 * BS_U32) * 4)   // 67584

// Scratch (no allocations allowed anywhere)
__device__ uint32_t g_Atf[(size_t)B_SESS * B_SESS];  // A in tf32 bits
__device__ uint32_t g_ttf[B_SESS * E];               // (s @ W^T) in tf32 bits
__device__ float g_s[B_SESS * E];
__device__ float g_acc[B_SESS * E];
__device__ float g_part[KSPLIT * B_SESS * E];
__device__ float g_d[B_SESS];

// ---------------------------------------------------------------------------
// PTX helpers (all plain sm_80+ features; no arch-'a' gating)
// ---------------------------------------------------------------------------
__device__ __forceinline__ uint32_t smem_u32(const void* p) {
    uint32_t a;
    asm("{ .reg .u64 t; cvta.to.shared.u64 t, %1; cvt.u32.u64 %0, t; }"
        : "=r"(a) : "l"(p));
    return a;
}
__device__ __forceinline__ uint32_t f2tf32(float f) {
    uint32_t u;
    asm("cvt.rn.tf32.f32 %0, %1;" : "=r"(u) : "f"(f));
    return u;
}
#define CP16(dst, src) \
    asm volatile("cp.async.cg.shared.global [%0], [%1], 16;" \
                 :: "r"(dst), "l"(src) : "memory")
#define CP_COMMIT() asm volatile("cp.async.commit_group;" ::: "memory")
#define CP_WAIT1()  asm volatile("cp.async.wait_group 1;" ::: "memory")
#define CP_WAIT0()  asm volatile("cp.async.wait_group 0;" ::: "memory")

__device__ __forceinline__ void mma_tf32(float* c, const uint32_t* a,
                                         const uint32_t* b) {
    asm volatile(
        "mma.sync.aligned.m16n8k8.row.col.f32.tf32.tf32.f32 "
        "{%0,%1,%2,%3},{%4,%5,%6,%7},{%8,%9},{%0,%1,%2,%3};"
        : "+f"(c[0]), "+f"(c[1]), "+f"(c[2]), "+f"(c[3])
        : "r"(a[0]), "r"(a[1]), "r"(a[2]), "r"(a[3]), "r"(b[0]), "r"(b[1]));
}

// ---------------------------------------------------------------------------
// 0. One-time: A -> tf32(RN) bits
// ---------------------------------------------------------------------------
__global__ void cvtA_kernel(const float* __restrict__ A) {
    size_t i = ((size_t)blockIdx.x * blockDim.x + threadIdx.x) * 4;
    float4 v = *reinterpret_cast<const float4*>(A + i);
    uint4 u = make_uint4(f2tf32(v.x), f2tf32(v.y), f2tf32(v.z), f2tf32(v.w));
    *reinterpret_cast<uint4*>(g_Atf + i) = u;
}

// ---------------------------------------------------------------------------
// 1. Fused ragged gather + mean pool. One block per session.
// ---------------------------------------------------------------------------
__global__ void gather_mean_kernel(const float* __restrict__ emb,
                                   const int* __restrict__ items,
                                   const float* __restrict__ slen) {
    __shared__ int sidx[MAX_LEN];
    int b = blockIdx.x;
    int tid = threadIdx.x;
    for (int i = tid; i < MAX_LEN; i += blockDim.x)
        sidx[i] = items[(size_t)b * MAX_LEN + i];
    __syncthreads();
    if (tid < E) {
        float acc = 0.0f;
        #pragma unroll 4
        for (int t = 0; t < MAX_LEN; ++t) {
            int idx = sidx[t];
            if (idx > 0 && idx <= N_ITEMS)
                acc += emb[((size_t)(idx - 1)) * E + tid];
        }
        float v = acc / slen[b];
        g_s[(size_t)b * E + tid] = v;
        g_acc[(size_t)b * E + tid] = v;
    }
}

// ---------------------------------------------------------------------------
// 2. diag(D)
// ---------------------------------------------------------------------------
__global__ void diag_kernel(const float* __restrict__ D) {
    int i = blockIdx.x * blockDim.x + threadIdx.x;
    if (i < B_SESS)
        g_d[i] = D[(size_t)i * B_SESS + i];
}

// ---------------------------------------------------------------------------
// 3. t = s @ W^T -> tf32 bits. One block per session row.
// ---------------------------------------------------------------------------
__global__ void small_mm_kernel(const float* __restrict__ W) {
    __shared__ float srow[E];
    int b = blockIdx.x;
    int o = threadIdx.x;   // blockDim.x == E
    srow[o] = g_s[(size_t)b * E + o];
    __syncthreads();
    const float4* w4 = reinterpret_cast<const float4*>(W + (size_t)o * E);
    const float4* s4 = reinterpret_cast<const float4*>(srow);
    float acc = 0.0f;
    #pragma unroll
    for (int i = 0; i < E / 4; ++i) {
        float4 w = w4[i];
        float4 s = s4[i];
        acc = fmaf(w.x, s.x, acc);
        acc = fmaf(w.y, s.y, acc);
        acc = fmaf(w.z, s.z, acc);
        acc = fmaf(w.w, s.w, acc);
    }
    g_ttf[(size_t)b * E + o] = f2tf32(acc);
}

// ---------------------------------------------------------------------------
// 4. Tensor-core GEMM: part[split] = A[:, kc] @ t[kc, :]   (tf32 mma.sync)
//    grid (32, KSPLIT), 256 threads = 8 warps in 4(M) x 2(N).
//    Each warp: 2 m16 tiles x 7 n8 tiles. cp.async double-buffered BK=32.
// ---------------------------------------------------------------------------
__global__ void __launch_bounds__(256)
big_mm_mma() {
    extern __shared__ uint32_t smem[];
    uint32_t* As = smem;                   // [2][128][AS_STRIDE]
    uint32_t* Bs = smem + 2 * AS_U32;      // [2][32][BS_STRIDE]

    const int tid = threadIdx.x;
    const int lane = tid & 31;
    const int wid = tid >> 5;
    const int wm = wid & 3;                // 4 M-strips of 32 rows
    const int wn = wid >> 2;               // 2 N-strips of 56 cols
    const int g = lane >> 2;               // group id 0..7
    const int t = lane & 3;                // thread-in-group 0..3
    const int row0 = blockIdx.x * 128;
    const int kbase = blockIdx.y * KCHUNK;

    float acc[2][7][4];
    #pragma unroll
    for (int i = 0; i < 2; ++i)
        #pragma unroll
        for (int j = 0; j < 7; ++j)
            #pragma unroll
            for (int k = 0; k < 4; ++k) acc[i][j][k] = 0.0f;

    // ---- cp.async stage: A 128x32, B 32x112 (raw tf32 bits) ----
    auto stage = [&](int buf, int k0) {
        uint32_t* Ab = As + buf * AS_U32;
        uint32_t* Bb = Bs + buf * BS_U32;
        #pragma unroll
        for (int j = 0; j < 4; ++j) {          // A: 1024 16B chunks
            int c = tid + j * 256;
            int r = c >> 3, cc = c & 7;
            uint32_t dst = smem_u32(&Ab[r * AS_STRIDE + cc * 4]);
            CP16(dst, &g_Atf[(size_t)(row0 + r) * B_SESS + k0 + cc * 4]);
        }
        #pragma unroll
        for (int j = 0; j < 4; ++j) {          // B: 896 16B chunks
            int c = tid + j * 256;
            if (c < 896) {
                int r = c / 28, cc = c % 28;
                uint32_t dst = smem_u32(&Bb[r * BS_STRIDE + cc * 4]);
                CP16(dst, &g_ttf[(size_t)(k0 + r) * E + cc * 4]);
            }
        }
    };

    auto compute = [&](int buf) {
        const uint32_t* A_ = As + buf * AS_U32;
        const uint32_t* B_ = Bs + buf * BS_U32;
        #pragma unroll
        for (int ks = 0; ks < 4; ++ks) {
            uint32_t a[2][4], b[7][2];
            #pragma unroll
            for (int i = 0; i < 2; ++i) {
                int r = wm * 32 + i * 16 + g;
                int c = ks * 8 + t;
                a[i][0] = A_[r * AS_STRIDE + c];
                a[i][1] = A_[(r + 8) * AS_STRIDE + c];
                a[i][2] = A_[r * AS_STRIDE + c + 4];
                a[i][3] = A_[(r + 8) * AS_STRIDE + c + 4];
            }
            #pragma unroll
            for (int j = 0; j < 7; ++j) {
                int n = wn * 56 + j * 8 + g;
                int r = ks * 8 + t;
                b[j][0] = B_[r * BS_STRIDE + n];
                b[j][1] = B_[(r + 4) * BS_STRIDE + n];
            }
            #pragma unroll
            for (int i = 0; i < 2; ++i)
                #pragma unroll
                for (int j = 0; j < 7; ++j)
                    mma_tf32(acc[i][j], a[i], b[j]);
        }
    };

    stage(0, kbase);
    CP_COMMIT();
    for (int s = 0; s < NSTAGE; ++s) {
        if (s + 1 < NSTAGE) {
            stage((s + 1) & 1, kbase + (s + 1) * BK);
            CP_COMMIT();
            CP_WAIT1();
        } else {
            CP_WAIT0();
        }
        __syncthreads();
        compute(s & 1);
        __syncthreads();
    }

    // epilogue -> split-K partials
    float* part = g_part + (size_t)blockIdx.y * B_SESS * E;
    #pragma unroll
    for (int i = 0; i < 2; ++i) {
        int r = row0 + wm * 32 + i * 16 + g;
        #pragma unroll
        for (int j = 0; j < 7; ++j) {
            int n = wn * 56 + j * 8 + 2 * t;
            *reinterpret_cast<float2*>(&part[(size_t)r * E + n]) =
                make_float2(acc[i][j][0], acc[i][j][1]);
            *reinterpret_cast<float2*>(&part[(size_t)(r + 8) * E + n]) =
                make_float2(acc[i][j][2], acc[i][j][3]);
        }
    }
}

// ---------------------------------------------------------------------------
// 5. Reduce split-K partials + diagonal scale -> g_s
// ---------------------------------------------------------------------------
__global__ void reducek_kernel() {
    int idx = blockIdx.x * blockDim.x + threadIdx.x;
    if (idx >= B_SESS * E) return;
    float sum = 0.0f;
    #pragma unroll
    for (int c = 0; c < KSPLIT; ++c)
        sum += g_part[(size_t)c * B_SESS * E + idx];
    int r = idx / E;
    g_s[idx] = g_d[r] * sum;
}

// ---------------------------------------------------------------------------
// 6. Row L2-normalize g_s, add into g_acc. One warp per row.
// ---------------------------------------------------------------------------
__global__ void norm_acc_kernel() {
    int warp = threadIdx.x >> 5;
    int lane = threadIdx.x & 31;
    int r = blockIdx.x * 4 + warp;
    if (r >= B_SESS) return;
    const float4* row = reinterpret_cast<const float4*>(g_s + (size_t)r * E);
    float4 v = make_float4(0.f, 0.f, 0.f, 0.f);
    if (lane < E / 4) v = row[lane];
    float ss = v.x * v.x + v.y * v.y + v.z * v.z + v.w * v.w;
    #pragma unroll
    for (int o = 16; o; o >>= 1) ss += __shfl_xor_sync(0xffffffffu, ss, o);
    float f = 1.0f / fmaxf(sqrtf(ss), 1e-12f);
    if (lane < E / 4) {
        float4* arow = reinterpret_cast<float4*>(g_acc + (size_t)r * E);
        float4 a = arow[lane];
        a.x = fmaf(v.x, f, a.x);
        a.y = fmaf(v.y, f, a.y);
        a.z = fmaf(v.z, f, a.z);
        a.w = fmaf(v.w, f, a.w);
        arow[lane] = a;
    }
}

// ---------------------------------------------------------------------------
// 7. out = g_acc / (LAYERS + 1)
// ---------------------------------------------------------------------------
__global__ void scale_out_kernel(float* __restrict__ out) {
    int idx = blockIdx.x * blockDim.x + threadIdx.x;
    if (idx < B_SESS * E)
        out[idx] = g_acc[idx] * 0.25f;
}

// ---------------------------------------------------------------------------
extern "C" void kernel_launch(void* const* d_in, const int* in_sizes, int n_in,
                              void* d_out, int out_size) {
    const float* emb   = (const float*)d_in[0];     // [100000,112]
    const float* D     = (const float*)d_in[1];     // [4096,4096]
    const float* A     = (const float*)d_in[2];     // [4096,4096]
    const float* slen  = (const float*)d_in[3];     // [4096,1]
    const float* Ws    = (const float*)d_in[4];     // [3,112,112]
    const int*   items = (const int*)d_in[5];       // [4096,200] int32
    float* out = (float*)d_out;

    cudaFuncSetAttribute(big_mm_mma, cudaFuncAttributeMaxDynamicSharedMemorySize,
                         SMEM_BYTES);

    cvtA_kernel<<<(B_SESS * (size_t)B_SESS) / 4 / 256, 256>>>(A);
    gather_mean_kernel<<<B_SESS, 128>>>(emb, items, slen);
    diag_kernel<<<(B_SESS + 255) / 256, 256>>>(D);

    for (int l = 0; l < LAYERS; ++l) {
        small_mm_kernel<<<B_SESS, E>>>(Ws + (size_t)l * E * E);
        big_mm_mma<<<dim3(B_SESS / 128, KSPLIT), 256, SMEM_BYTES>>>();
        reducek_kernel<<<(B_SESS * E + 255) / 256, 256>>>();
        norm_acc_kernel<<<B_SESS / 4, 128>>>();
    }

    scale_out_kernel<<<(B_SESS * E + 255) / 256, 256>>>(out);
}

// round 6
// speedup vs baseline: 2.5302x; 1.1879x over previous
#include <cuda_runtime.h>
#include <cstdint>

#define B_SESS 4096
#define MAX_LEN 200
#define E 112
#define N_ITEMS 100000
#define LAYERS 3
#define KSPLIT 8
#define KCHUNK (B_SESS / KSPLIT)   // 512
#define BK 32
#define NSTAGE (KCHUNK / BK)       // 16

// big_mm smem staging (uint32 units); strides conflict-free for fragment LDS.
#define AS_STRIDE 36
#define BS_STRIDE 120
#define AS_U32 (128 * AS_STRIDE)
#define BS_U32 (32 * BS_STRIDE)
#define SMEM_BYTES ((2 * AS_U32 + 2 * BS_U32) * 4)   // 67584

// small_mm smem: S tile [128][116], W^T [112][120]
#define SS_STRIDE 116
#define WS_STRIDE 120
#define SM2_BYTES ((128 * SS_STRIDE + 112 * WS_STRIDE) * 4)   // 113152

// prep kernel grid partition
#define NB_GATHER 4096
#define NB_CVT    16384                       // 16M elems / (256*4)
#define NB_DIAG   16
#define NB_PREP   (NB_GATHER + NB_CVT + NB_DIAG)

// Scratch
__device__ uint32_t g_Atf[(size_t)B_SESS * B_SESS];  // A in tf32 bits
__device__ uint32_t g_ttf[B_SESS * E];               // (s @ W^T) tf32 bits
__device__ float g_s[B_SESS * E];
__device__ float g_acc[B_SESS * E];
__device__ float g_part[KSPLIT * B_SESS * E];
__device__ float g_d[B_SESS];

// ---------------------------------------------------------------------------
// PTX helpers (plain sm_80+; no arch-'a' gating)
// ---------------------------------------------------------------------------
__device__ __forceinline__ uint32_t smem_u32(const void* p) {
    uint32_t a;
    asm("{ .reg .u64 t; cvta.to.shared.u64 t, %1; cvt.u32.u64 %0, t; }"
        : "=r"(a) : "l"(p));
    return a;
}
__device__ __forceinline__ uint32_t f2tf32(float f) {
    uint32_t u;
    asm("cvt.rn.tf32.f32 %0, %1;" : "=r"(u) : "f"(f));
    return u;
}
#define CP16(dst, src) \
    asm volatile("cp.async.cg.shared.global [%0], [%1], 16;" \
                 :: "r"(dst), "l"(src) : "memory")
#define CP_COMMIT() asm volatile("cp.async.commit_group;" ::: "memory")
#define CP_WAIT1()  asm volatile("cp.async.wait_group 1;" ::: "memory")
#define CP_WAIT0()  asm volatile("cp.async.wait_group 0;" ::: "memory")

__device__ __forceinline__ void mma_tf32(float* c, const uint32_t* a,
                                         const uint32_t* b) {
    asm volatile(
        "mma.sync.aligned.m16n8k8.row.col.f32.tf32.tf32.f32 "
        "{%0,%1,%2,%3},{%4,%5,%6,%7},{%8,%9},{%0,%1,%2,%3};"
        : "+f"(c[0]), "+f"(c[1]), "+f"(c[2]), "+f"(c[3])
        : "r"(a[0]), "r"(a[1]), "r"(a[2]), "r"(a[3]), "r"(b[0]), "r"(b[1]));
}

// ---------------------------------------------------------------------------
// 1. Prep: gather+mean (L2-bound) || cvtA (DRAM-bound) || diag, one grid.
// ---------------------------------------------------------------------------
__global__ void prep_kernel(const float* __restrict__ A,
                            const float* __restrict__ emb,
                            const int* __restrict__ items,
                            const float* __restrict__ slen,
                            const float* __restrict__ D) {
    int blk = blockIdx.x;
    int tid = threadIdx.x;

    if (blk < NB_GATHER) {                       // ---- gather + mean pool ----
        __shared__ int sidx[MAX_LEN];
        int b = blk;
        for (int i = tid; i < MAX_LEN; i += blockDim.x)
            sidx[i] = items[(size_t)b * MAX_LEN + i];
        __syncthreads();
        if (tid < E) {
            float acc = 0.0f;
            #pragma unroll 4
            for (int t = 0; t < MAX_LEN; ++t) {
                int idx = sidx[t];
                if (idx > 0 && idx <= N_ITEMS)
                    acc += emb[((size_t)(idx - 1)) * E + tid];
            }
            float v = acc / slen[b];
            g_s[(size_t)b * E + tid] = v;
            g_acc[(size_t)b * E + tid] = v;
        }
    } else if (blk < NB_GATHER + NB_CVT) {       // ---- A -> tf32 bits ----
        size_t i = (((size_t)(blk - NB_GATHER)) * 256 + tid) * 4;
        float4 v = *reinterpret_cast<const float4*>(A + i);
        uint4 u = make_uint4(f2tf32(v.x), f2tf32(v.y), f2tf32(v.z), f2tf32(v.w));
        *reinterpret_cast<uint4*>(g_Atf + i) = u;
    } else {                                     // ---- diag(D) ----
        int i = (blk - NB_GATHER - NB_CVT) * 256 + tid;
        if (i < B_SESS)
            g_d[i] = D[(size_t)i * B_SESS + i];
    }
}

// ---------------------------------------------------------------------------
// 2. small GEMM on tensor cores: g_ttf = tf32(g_s @ W^T)
//    grid 32 x 256 thr. M=128/CTA, N=112, K=112 (14 k-steps).
// ---------------------------------------------------------------------------
__global__ void __launch_bounds__(256)
small_mm_tc(const float* __restrict__ W) {
    extern __shared__ uint32_t sm2[];
    uint32_t* Ss = sm2;                          // [128][SS_STRIDE]
    uint32_t* Wt = sm2 + 128 * SS_STRIDE;        // [112][WS_STRIDE] (k-major)

    const int tid = threadIdx.x;
    const int lane = tid & 31;
    const int wid = tid >> 5;
    const int wm = wid & 3;
    const int wn = wid >> 2;
    const int g = lane >> 2;
    const int t = lane & 3;
    const int row0 = blockIdx.x * 128;

    for (int idx = tid; idx < 128 * E; idx += 256) {
        int r = idx / E, c = idx % E;
        Ss[r * SS_STRIDE + c] = f2tf32(g_s[(size_t)(row0 + r) * E + c]);
    }
    for (int idx = tid; idx < E * E; idx += 256) {
        int o = idx / E, i = idx % E;            // W[o][i] -> Wt[i][o]
        Wt[i * WS_STRIDE + o] = f2tf32(W[(size_t)o * E + i]);
    }
    __syncthreads();

    float acc[2][7][4];
    #pragma unroll
    for (int i = 0; i < 2; ++i)
        #pragma unroll
        for (int j = 0; j < 7; ++j)
            #pragma unroll
            for (int k = 0; k < 4; ++k) acc[i][j][k] = 0.0f;

    #pragma unroll
    for (int ks = 0; ks < 14; ++ks) {
        uint32_t a[2][4], b[7][2];
        #pragma unroll
        for (int i = 0; i < 2; ++i) {
            int r = wm * 32 + i * 16 + g;
            int c = ks * 8 + t;
            a[i][0] = Ss[r * SS_STRIDE + c];
            a[i][1] = Ss[(r + 8) * SS_STRIDE + c];
            a[i][2] = Ss[r * SS_STRIDE + c + 4];
            a[i][3] = Ss[(r + 8) * SS_STRIDE + c + 4];
        }
        #pragma unroll
        for (int j = 0; j < 7; ++j) {
            int n = wn * 56 + j * 8 + g;
            int r = ks * 8 + t;
            b[j][0] = Wt[r * WS_STRIDE + n];
            b[j][1] = Wt[(r + 4) * WS_STRIDE + n];
        }
        #pragma unroll
        for (int i = 0; i < 2; ++i)
            #pragma unroll
            for (int j = 0; j < 7; ++j)
                mma_tf32(acc[i][j], a[i], b[j]);
    }

    #pragma unroll
    for (int i = 0; i < 2; ++i) {
        int r = row0 + wm * 32 + i * 16 + g;
        #pragma unroll
        for (int j = 0; j < 7; ++j) {
            int n = wn * 56 + j * 8 + 2 * t;
            *reinterpret_cast<uint2*>(&g_ttf[(size_t)r * E + n]) =
                make_uint2(f2tf32(acc[i][j][0]), f2tf32(acc[i][j][1]));
            *reinterpret_cast<uint2*>(&g_ttf[(size_t)(r + 8) * E + n]) =
                make_uint2(f2tf32(acc[i][j][2]), f2tf32(acc[i][j][3]));
        }
    }
}

// ---------------------------------------------------------------------------
// 3. Big tensor-core GEMM: part[split] = A[:, kc] @ t[kc, :]
// ---------------------------------------------------------------------------
__global__ void __launch_bounds__(256)
big_mm_mma() {
    extern __shared__ uint32_t smem[];
    uint32_t* As = smem;                   // [2][128][AS_STRIDE]
    uint32_t* Bs = smem + 2 * AS_U32;      // [2][32][BS_STRIDE]

    const int tid = threadIdx.x;
    const int lane = tid & 31;
    const int wid = tid >> 5;
    const int wm = wid & 3;
    const int wn = wid >> 2;
    const int g = lane >> 2;
    const int t = lane & 3;
    const int row0 = blockIdx.x * 128;
    const int kbase = blockIdx.y * KCHUNK;

    float acc[2][7][4];
    #pragma unroll
    for (int i = 0; i < 2; ++i)
        #pragma unroll
        for (int j = 0; j < 7; ++j)
            #pragma unroll
            for (int k = 0; k < 4; ++k) acc[i][j][k] = 0.0f;

    auto stage = [&](int buf, int k0) {
        uint32_t* Ab = As + buf * AS_U32;
        uint32_t* Bb = Bs + buf * BS_U32;
        #pragma unroll
        for (int j = 0; j < 4; ++j) {
            int c = tid + j * 256;
            int r = c >> 3, cc = c & 7;
            uint32_t dst = smem_u32(&Ab[r * AS_STRIDE + cc * 4]);
            CP16(dst, &g_Atf[(size_t)(row0 + r) * B_SESS + k0 + cc * 4]);
        }
        #pragma unroll
        for (int j = 0; j < 4; ++j) {
            int c = tid + j * 256;
            if (c < 896) {
                int r = c / 28, cc = c % 28;
                uint32_t dst = smem_u32(&Bb[r * BS_STRIDE + cc * 4]);
                CP16(dst, &g_ttf[(size_t)(k0 + r) * E + cc * 4]);
            }
        }
    };

    auto compute = [&](int buf) {
        const uint32_t* A_ = As + buf * AS_U32;
        const uint32_t* B_ = Bs + buf * BS_U32;
        #pragma unroll
        for (int ks = 0; ks < 4; ++ks) {
            uint32_t a[2][4], b[7][2];
            #pragma unroll
            for (int i = 0; i < 2; ++i) {
                int r = wm * 32 + i * 16 + g;
                int c = ks * 8 + t;
                a[i][0] = A_[r * AS_STRIDE + c];
                a[i][1] = A_[(r + 8) * AS_STRIDE + c];
                a[i][2] = A_[r * AS_STRIDE + c + 4];
                a[i][3] = A_[(r + 8) * AS_STRIDE + c + 4];
            }
            #pragma unroll
            for (int j = 0; j < 7; ++j) {
                int n = wn * 56 + j * 8 + g;
                int r = ks * 8 + t;
                b[j][0] = B_[r * BS_STRIDE + n];
                b[j][1] = B_[(r + 4) * BS_STRIDE + n];
            }
            #pragma unroll
            for (int i = 0; i < 2; ++i)
                #pragma unroll
                for (int j = 0; j < 7; ++j)
                    mma_tf32(acc[i][j], a[i], b[j]);
        }
    };

    stage(0, kbase);
    CP_COMMIT();
    for (int s = 0; s < NSTAGE; ++s) {
        if (s + 1 < NSTAGE) {
            stage((s + 1) & 1, kbase + (s + 1) * BK);
            CP_COMMIT();
            CP_WAIT1();
        } else {
            CP_WAIT0();
        }
        __syncthreads();
        compute(s & 1);
        __syncthreads();
    }

    float* part = g_part + (size_t)blockIdx.y * B_SESS * E;
    #pragma unroll
    for (int i = 0; i < 2; ++i) {
        int r = row0 + wm * 32 + i * 16 + g;
        #pragma unroll
        for (int j = 0; j < 7; ++j) {
            int n = wn * 56 + j * 8 + 2 * t;
            *reinterpret_cast<float2*>(&part[(size_t)r * E + n]) =
                make_float2(acc[i][j][0], acc[i][j][1]);
            *reinterpret_cast<float2*>(&part[(size_t)(r + 8) * E + n]) =
                make_float2(acc[i][j][2], acc[i][j][3]);
        }
    }
}

// ---------------------------------------------------------------------------
// 4. Fused: split-K reduce + diag scale + L2-normalize + acc (+ final out)
//    One warp per row; block = 8 warps; grid = 512.
// ---------------------------------------------------------------------------
__global__ void reduce_norm_kernel(float* __restrict__ out, int last) {
    int warp = threadIdx.x >> 5;
    int lane = threadIdx.x & 31;
    int r = blockIdx.x * 8 + warp;

    float4 v = make_float4(0.f, 0.f, 0.f, 0.f);
    if (lane < E / 4) {
        #pragma unroll
        for (int c = 0; c < KSPLIT; ++c) {
            float4 p = *reinterpret_cast<const float4*>(
                &g_part[(size_t)c * B_SESS * E + (size_t)r * E + lane * 4]);
            v.x += p.x; v.y += p.y; v.z += p.z; v.w += p.w;
        }
        float d = g_d[r];
        v.x *= d; v.y *= d; v.z *= d; v.w *= d;
        *reinterpret_cast<float4*>(&g_s[(size_t)r * E + lane * 4]) = v;
    }
    float ss = v.x * v.x + v.y * v.y + v.z * v.z + v.w * v.w;
    #pragma unroll
    for (int o = 16; o; o >>= 1) ss += __shfl_xor_sync(0xffffffffu, ss, o);
    float f = 1.0f / fmaxf(sqrtf(ss), 1e-12f);
    if (lane < E / 4) {
        float4* arow = reinterpret_cast<float4*>(g_acc + (size_t)r * E);
        float4 a = arow[lane];
        a.x = fmaf(v.x, f, a.x);
        a.y = fmaf(v.y, f, a.y);
        a.z = fmaf(v.z, f, a.z);
        a.w = fmaf(v.w, f, a.w);
        arow[lane] = a;
        if (last) {
            float4 o4 = make_float4(a.x * 0.25f, a.y * 0.25f,
                                    a.z * 0.25f, a.w * 0.25f);
            *reinterpret_cast<float4*>(&out[(size_t)r * E + lane * 4]) = o4;
        }
    }
}

// ---------------------------------------------------------------------------
extern "C" void kernel_launch(void* const* d_in, const int* in_sizes, int n_in,
                              void* d_out, int out_size) {
    const float* emb   = (const float*)d_in[0];     // [100000,112]
    const float* D     = (const float*)d_in[1];     // [4096,4096]
    const float* A     = (const float*)d_in[2];     // [4096,4096]
    const float* slen  = (const float*)d_in[3];     // [4096,1]
    const float* Ws    = (const float*)d_in[4];     // [3,112,112]
    const int*   items = (const int*)d_in[5];       // [4096,200] int32
    float* out = (float*)d_out;

    cudaFuncSetAttribute(big_mm_mma, cudaFuncAttributeMaxDynamicSharedMemorySize,
                         SMEM_BYTES);
    cudaFuncSetAttribute(small_mm_tc, cudaFuncAttributeMaxDynamicSharedMemorySize,
                         SM2_BYTES);

    prep_kernel<<<NB_PREP, 256>>>(A, emb, items, slen, D);

    for (int l = 0; l < LAYERS; ++l) {
        small_mm_tc<<<32, 256, SM2_BYTES>>>(Ws + (size_t)l * E * E);
        big_mm_mma<<<dim3(B_SESS / 128, KSPLIT), 256, SMEM_BYTES>>>();
        reduce_norm_kernel<<<B_SESS / 8, 256>>>(out, l == LAYERS - 1);
    }
}